// round 3
// baseline (speedup 1.0000x reference)
#include <cuda_runtime.h>
#include <math.h>

// ---------------- problem constants (from setup_inputs) ----------------
#define Bv 8
#define Cv 2
#define Tv 1440000
#define Mv 1024
#define Nv 2048
#define Fv 1408                      // ceil((T+M)/M)
#define Rv (Bv*Fv*Cv)                // 22528 rows
#define NFRAME (Bv*Fv)               // 11264 (b,f) frames

// ---------------- static scratch (no allocation allowed) ----------------
__device__ float g_Cm [Nv*Mv];            // 8 MB   cos matrix, row-major (n,k)
__device__ float g_CmT[Mv*Nv];            // 8 MB   transpose, row-major (k,n)
__device__ float g_W  [Nv];               // window
__device__ float g_FR [(size_t)Rv*Nv];    // 184 MB windowed frames
__device__ float g_CO [(size_t)Rv*Mv];    // 92 MB  MDCT coeffs
__device__ float g_GA [NFRAME];           // per-(b,f) gain
__device__ float g_DQ [(size_t)Rv*Mv];    // 92 MB  dequantized coeffs
__device__ float g_TD [(size_t)Rv*Nv];    // 184 MB inverse transform

// ---------------- tables: must mirror reference fp32 expression order ----
__global__ void k_tables() {
    int idx = blockIdx.x * blockDim.x + threadIdx.x;
    if (idx >= Nv * Mv) return;
    int n = idx >> 10;
    int k = idx & 1023;
    const float c0 = (float)(3.14159265358979323846 / 1024.0);  // fl32(pi/M)
    float a   = c0 * ((float)n + 512.5f);       // fl32(c0*(n+0.5+M/2))
    float arg = a * ((float)k + 0.5f);          // fl32(a*(k+0.5))
    float v   = cosf(arg);
    g_Cm[idx] = v;
    g_CmT[k * Nv + n] = v;
    if (idx < Nv) {
        const float c1 = (float)(3.14159265358979323846 / 2048.0);
        g_W[idx] = sinf(c1 * ((float)idx + 0.5f));
    }
}

// ---------------- frame + window (handles left pad M and right zero pad) --
__global__ void k_frames(const float* __restrict__ audio) {
    long long idx = (long long)blockIdx.x * blockDim.x + threadIdx.x;
    if (idx >= (long long)Rv * Nv) return;
    int n   = (int)(idx & (Nv - 1));
    int row = (int)(idx >> 11);
    int c   = row & 1;          // C = 2
    int bf  = row >> 1;
    int f   = bf % Fv;
    int b   = bf / Fv;
    int src = f * Mv + n - Mv;  // padded pos minus left pad
    float x = (src >= 0 && src < Tv)
                ? audio[(size_t)(b * Cv + c) * Tv + src] : 0.0f;
    g_FR[idx] = x * g_W[n];
}

// ---------------- fp32 SGEMM: 128x128x8 tiles, double-buffered, 8x8/thread
// Chunked accumulation: a fresh accumulator bank per 256 K-steps (32 tiles),
// folded into a running total. Cuts my summation error ~6x below sequential-K
// so |mine - ref| is dominated by the reference's own rounding error.
template<int K, int NC, bool SCALE>
__device__ __forceinline__ void sgemm_body(const float* __restrict__ A,
                                           const float* __restrict__ B,
                                           float* __restrict__ Co) {
    __shared__ float As[2][8][128];
    __shared__ float Bs[2][8][128];
    const int tid  = threadIdx.x;
    const int bx   = blockIdx.x;   // N tile
    const int by   = blockIdx.y;   // M tile
    const int arow = tid >> 1;
    const int acol = (tid & 1) << 2;
    const int brow = tid >> 5;
    const int bcol = (tid & 31) << 2;
    const int tx   = tid & 15;
    const int ty   = tid >> 4;

    const float* Ap = A + (size_t)(by * 128 + arow) * K + acol;
    const float* Bp = B + (size_t)brow * NC + bx * 128 + bcol;

    float accT[8][8];   // running total (folded every 32 tiles)
    float accC[8][8];   // current chunk
#pragma unroll
    for (int i = 0; i < 8; i++)
#pragma unroll
        for (int j = 0; j < 8; j++) { accT[i][j] = 0.0f; accC[i][j] = 0.0f; }

    // prologue: tile 0
    {
        float4 a4 = *(const float4*)Ap;
        float4 b4 = *(const float4*)Bp;
        As[0][acol + 0][arow] = a4.x;
        As[0][acol + 1][arow] = a4.y;
        As[0][acol + 2][arow] = a4.z;
        As[0][acol + 3][arow] = a4.w;
        *(float4*)&Bs[0][brow][bcol] = b4;
    }
    __syncthreads();

    const int NT = K / 8;
    int buf = 0;
#pragma unroll 1
    for (int t = 0; t < NT; ++t) {
        float4 na, nb4;
        const bool have_next = (t + 1 < NT);
        if (have_next) {
            na  = *(const float4*)(Ap + (size_t)(t + 1) * 8);
            nb4 = *(const float4*)(Bp + (size_t)(t + 1) * 8 * NC);
        }
#pragma unroll
        for (int k = 0; k < 8; k++) {
            float ra[8], rb[8];
            *(float4*)&ra[0] = *(const float4*)&As[buf][k][ty * 8];
            *(float4*)&ra[4] = *(const float4*)&As[buf][k][ty * 8 + 4];
            *(float4*)&rb[0] = *(const float4*)&Bs[buf][k][tx * 8];
            *(float4*)&rb[4] = *(const float4*)&Bs[buf][k][tx * 8 + 4];
#pragma unroll
            for (int i = 0; i < 8; i++)
#pragma unroll
                for (int j = 0; j < 8; j++)
                    accC[i][j] = fmaf(ra[i], rb[j], accC[i][j]);
        }
        if (((t + 1) & 31) == 0) {      // fold chunk every 32 tiles (256 k)
#pragma unroll
            for (int i = 0; i < 8; i++)
#pragma unroll
                for (int j = 0; j < 8; j++) {
                    accT[i][j] += accC[i][j];
                    accC[i][j] = 0.0f;
                }
        }
        if (have_next) {
            int nbuf = buf ^ 1;
            As[nbuf][acol + 0][arow] = na.x;
            As[nbuf][acol + 1][arow] = na.y;
            As[nbuf][acol + 2][arow] = na.z;
            As[nbuf][acol + 3][arow] = na.w;
            *(float4*)&Bs[nbuf][brow][bcol] = nb4;
            __syncthreads();
            buf = nbuf;
        }
    }

    const float s = SCALE ? (2.0f / 1024.0f) : 1.0f;   // exact power of two
    float* Cp = Co + (size_t)(by * 128 + ty * 8) * NC + bx * 128 + tx * 8;
#pragma unroll
    for (int i = 0; i < 8; i++) {
        float4 o0, o1;
        o0.x = accT[i][0] * s; o0.y = accT[i][1] * s;
        o0.z = accT[i][2] * s; o0.w = accT[i][3] * s;
        o1.x = accT[i][4] * s; o1.y = accT[i][5] * s;
        o1.z = accT[i][6] * s; o1.w = accT[i][7] * s;
        *(float4*)(Cp + (size_t)i * NC)     = o0;
        *(float4*)(Cp + (size_t)i * NC + 4) = o1;
    }
}

__global__ __launch_bounds__(256, 1) void k_gemm_fwd() {
    sgemm_body<Nv, Mv, false>(g_FR, g_Cm, g_CO);     // coeffs = frames @ Cm
}
__global__ __launch_bounds__(256, 1) void k_gemm_inv() {
    sgemm_body<Mv, Nv, true>(g_DQ, g_CmT, g_TD);     // td = (2/M) * dq @ Cm^T
}

// ---------------- per-(b,f) gain binary search (8 iters, integers) -------
__global__ void k_gain() {
    __shared__ float ax[2048];
    __shared__ float red[256];
    __shared__ float s_lo, s_hi;
    const int bf  = blockIdx.x;                 // rows (b,f,c): frame contiguous
    const int tid = threadIdx.x;
    const float* cf = g_CO + (size_t)bf * 2048;
    for (int i = tid; i < 2048; i += 256)
        ax[i] = powf(fabsf(cf[i]), 0.75f);
    if (tid == 0) { s_lo = 0.0f; s_hi = 120.0f; }
    __syncthreads();

    const float TARGET = (float)(128000.0 * 1024.0 / 48000.0); // 2730.666...
    for (int it = 0; it < 8; it++) {
        float mid = floorf((s_lo + s_hi) * 0.5f);
        float inv = exp2f((-0.75f * mid) / 4.0f);
        float bits = 0.0f;
        for (int i = tid; i < 2048; i += 256) {
            float qm = rintf(ax[i] * inv);
            bits += (qm > 0.0f) ? (floorf(log2f(fmaxf(qm, 1.0f))) + 2.0f) : 1.0f;
        }
        red[tid] = bits;
        __syncthreads();
        for (int s = 128; s > 0; s >>= 1) {
            if (tid < s) red[tid] += red[tid + s];
            __syncthreads();
        }
        if (tid == 0) {
            if (red[0] > TARGET) s_lo = mid + 1.0f;
            else                 s_hi = mid;
        }
        __syncthreads();
    }
    if (tid == 0) g_GA[bf] = s_hi;
}

// ---------------- quantize + dequantize (power-law) ---------------------
__global__ void k_quant() {
    int idx = blockIdx.x * blockDim.x + threadIdx.x;
    if (idx >= Rv * Mv) return;
    int bf = idx >> 11;                       // ((bf*2+c)*1024+m) >> 11 == bf
    float g     = g_GA[bf];
    float scale = exp2f(g / 4.0f);
    float cv    = g_CO[idx];
    float s1 = (cv > 0.0f) ? 1.0f : ((cv < 0.0f) ? -1.0f : 0.0f);
    float qs = s1 * powf(fabsf(cv) / scale + 1e-9f, 0.75f);
    float q  = rintf(qs);
    float s2 = (q > 0.0f) ? 1.0f : ((q < 0.0f) ? -1.0f : 0.0f);
    g_DQ[idx] = s2 * powf(fabsf(q), (float)(4.0 / 3.0)) * scale;
}

// ---------------- window + overlap-add + crop --------------------------
__global__ void k_ola(float* __restrict__ out) {
    int idx = blockIdx.x * blockDim.x + threadIdx.x;
    if (idx >= Bv * Cv * Tv) return;
    int t  = idx % Tv;
    int bc = idx / Tv;
    int b  = bc >> 1;
    int c  = bc & 1;
    int fb = t >> 10;           // second-half frame
    int na = t & 1023;
    int rowa = (b * Fv + fb + 1) * Cv + c;   // first-half frame (fb+1 <= 1407 < F)
    int rowb = (b * Fv + fb) * Cv + c;
    float r1 = g_TD[(size_t)rowa * Nv + na]      * g_W[na];
    float r2 = g_TD[(size_t)rowb * Nv + na + Mv] * g_W[na + Mv];
    out[idx] = r1 + r2;
}

// ---------------- launch ------------------------------------------------
extern "C" void kernel_launch(void* const* d_in, const int* in_sizes, int n_in,
                              void* d_out, int out_size) {
    const float* audio = (const float*)d_in[0];
    float* out = (float*)d_out;

    k_tables<<<(Nv * Mv + 255) / 256, 256>>>();
    {
        long long tot = (long long)Rv * Nv;
        k_frames<<<(unsigned)((tot + 255) / 256), 256>>>(audio);
    }
    k_gemm_fwd<<<dim3(Mv / 128, Rv / 128), 256>>>();
    k_gain<<<NFRAME, 256>>>();
    k_quant<<<(Rv * Mv + 255) / 256, 256>>>();
    k_gemm_inv<<<dim3(Nv / 128, Rv / 128), 256>>>();
    k_ola<<<(Bv * Cv * Tv + 255) / 256, 256>>>(out);
}

// round 4
// speedup vs baseline: 1.0445x; 1.0445x over previous
#include <cuda_runtime.h>
#include <math.h>
#include <stdint.h>

// ---------------- problem constants (from setup_inputs) ----------------
#define Bv 8
#define Cv 2
#define Tv 1440000
#define Mv 1024
#define Nv 2048
#define Fv 1408                      // ceil((T+M)/M)
#define Rv (Bv*Fv*Cv)                // 22528 rows
#define NFRAME (Bv*Fv)               // 11264 (b,f) frames

// ---------------- static scratch (no allocation allowed) ----------------
__device__ float g_Cm [Nv*Mv];            // 8 MB   cos matrix, row-major (n,k)
__device__ float g_CmT[Mv*Nv];            // 8 MB   transpose, row-major (k,n)
__device__ float g_W  [Nv];               // window
__device__ float g_FR [(size_t)Rv*Nv];    // 184 MB windowed frames
__device__ float g_CO [(size_t)Rv*Mv];    // 92 MB  MDCT coeffs
__device__ float g_GA [NFRAME];           // per-(b,f) gain
__device__ float g_DQ [(size_t)Rv*Mv];    // 92 MB  dequantized coeffs
__device__ float g_TD [(size_t)Rv*Nv];    // 184 MB inverse transform

// ---------------- packed f32x2 helpers (Blackwell) ----------------------
__device__ __forceinline__ uint64_t splat2(float x) {
    uint64_t r; uint32_t u = __float_as_uint(x);
    asm("mov.b64 %0, {%1, %1};" : "=l"(r) : "r"(u));
    return r;
}
__device__ __forceinline__ void ffma2(uint64_t& d, uint64_t a, uint64_t b) {
    asm("fma.rn.f32x2 %0, %1, %2, %0;" : "+l"(d) : "l"(a), "l"(b));
}
__device__ __forceinline__ void fadd2(uint64_t& d, uint64_t a) {
    asm("add.rn.f32x2 %0, %0, %1;" : "+l"(d) : "l"(a));
}
__device__ __forceinline__ float lo32(uint64_t v) {
    return __uint_as_float((uint32_t)(v & 0xffffffffu));
}
__device__ __forceinline__ float hi32(uint64_t v) {
    return __uint_as_float((uint32_t)(v >> 32));
}

// ---------------- tables: must mirror reference fp32 expression order ----
__global__ void k_tables() {
    int idx = blockIdx.x * blockDim.x + threadIdx.x;
    if (idx >= Nv * Mv) return;
    int n = idx >> 10;
    int k = idx & 1023;
    const float c0 = (float)(3.14159265358979323846 / 1024.0);  // fl32(pi/M)
    float a   = c0 * ((float)n + 512.5f);       // fl32(c0*(n+0.5+M/2))
    float arg = a * ((float)k + 0.5f);          // fl32(a*(k+0.5))
    float v   = cosf(arg);
    g_Cm[idx] = v;
    g_CmT[k * Nv + n] = v;
    if (idx < Nv) {
        const float c1 = (float)(3.14159265358979323846 / 2048.0);
        g_W[idx] = sinf(c1 * ((float)idx + 0.5f));
    }
}

// ---------------- frame + window (handles left pad M and right zero pad) --
__global__ void k_frames(const float* __restrict__ audio) {
    long long idx = (long long)blockIdx.x * blockDim.x + threadIdx.x;
    if (idx >= (long long)Rv * Nv) return;
    int n   = (int)(idx & (Nv - 1));
    int row = (int)(idx >> 11);
    int c   = row & 1;          // C = 2
    int bf  = row >> 1;
    int f   = bf % Fv;
    int b   = bf / Fv;
    int src = f * Mv + n - Mv;  // padded pos minus left pad
    float x = (src >= 0 && src < Tv)
                ? audio[(size_t)(b * Cv + c) * Tv + src] : 0.0f;
    g_FR[idx] = x * g_W[n];
}

// ---------------- fp32x2 SGEMM: 128x128x8 tiles, double-buffered ---------
// Thread tile 8x8, accumulators packed as f32x2 pairs along the A-row axis:
// accp[i2][j] = (C[2*i2][j], C[2*i2+1][j]). Per-lane math is bitwise identical
// to the scalar round-3 kernel (same FMA chains, same chunk folding every
// 256 K-steps), but issues half the FMA instructions via fma.rn.f32x2.
template<int K, int NC, bool SCALE>
__device__ __forceinline__ void sgemm_body(const float* __restrict__ A,
                                           const float* __restrict__ B,
                                           float* __restrict__ Co) {
    __shared__ float As[2][8][128];
    __shared__ float Bs[2][8][128];
    const int tid  = threadIdx.x;
    const int bx   = blockIdx.x;   // N tile
    const int by   = blockIdx.y;   // M tile
    const int arow = tid >> 1;
    const int acol = (tid & 1) << 2;
    const int brow = tid >> 5;
    const int bcol = (tid & 31) << 2;
    const int tx   = tid & 15;
    const int ty   = tid >> 4;

    const float* Ap = A + (size_t)(by * 128 + arow) * K + acol;
    const float* Bp = B + (size_t)brow * NC + bx * 128 + bcol;

    uint64_t accT[4][8];   // running total (folded every 32 tiles), f32x2
    uint64_t accC[4][8];   // current chunk, f32x2
#pragma unroll
    for (int i = 0; i < 4; i++)
#pragma unroll
        for (int j = 0; j < 8; j++) { accT[i][j] = 0ull; accC[i][j] = 0ull; }

    // prologue: tile 0
    {
        float4 a4 = *(const float4*)Ap;
        float4 b4 = *(const float4*)Bp;
        As[0][acol + 0][arow] = a4.x;
        As[0][acol + 1][arow] = a4.y;
        As[0][acol + 2][arow] = a4.z;
        As[0][acol + 3][arow] = a4.w;
        *(float4*)&Bs[0][brow][bcol] = b4;
    }
    __syncthreads();

    const int NT = K / 8;
    int buf = 0;
#pragma unroll 1
    for (int t = 0; t < NT; ++t) {
        float4 na, nb4;
        const bool have_next = (t + 1 < NT);
        if (have_next) {
            na  = *(const float4*)(Ap + (size_t)(t + 1) * 8);
            nb4 = *(const float4*)(Bp + (size_t)(t + 1) * 8 * NC);
        }
#pragma unroll
        for (int k = 0; k < 8; k++) {
            // A pairs: adjacent floats -> 64-bit lanes, no packing needed
            uint64_t ap[4];
            {
                const ulonglong2* p2 =
                    (const ulonglong2*)&As[buf][k][ty * 8];
                ulonglong2 v0 = p2[0], v1 = p2[1];
                ap[0] = v0.x; ap[1] = v0.y; ap[2] = v1.x; ap[3] = v1.y;
            }
            float rb[8];
            *(float4*)&rb[0] = *(const float4*)&Bs[buf][k][tx * 8];
            *(float4*)&rb[4] = *(const float4*)&Bs[buf][k][tx * 8 + 4];
            uint64_t bs[8];
#pragma unroll
            for (int j = 0; j < 8; j++) bs[j] = splat2(rb[j]);
#pragma unroll
            for (int i = 0; i < 4; i++)
#pragma unroll
                for (int j = 0; j < 8; j++)
                    ffma2(accC[i][j], ap[i], bs[j]);
        }
        if (((t + 1) & 31) == 0) {      // fold chunk every 32 tiles (256 k)
#pragma unroll
            for (int i = 0; i < 4; i++)
#pragma unroll
                for (int j = 0; j < 8; j++) {
                    fadd2(accT[i][j], accC[i][j]);
                    accC[i][j] = 0ull;
                }
        }
        if (have_next) {
            int nbuf = buf ^ 1;
            As[nbuf][acol + 0][arow] = na.x;
            As[nbuf][acol + 1][arow] = na.y;
            As[nbuf][acol + 2][arow] = na.z;
            As[nbuf][acol + 3][arow] = na.w;
            *(float4*)&Bs[nbuf][brow][bcol] = nb4;
            __syncthreads();
            buf = nbuf;
        }
    }

    const float s = SCALE ? (2.0f / 1024.0f) : 1.0f;   // exact power of two
    float* Cp = Co + (size_t)(by * 128 + ty * 8) * NC + bx * 128 + tx * 8;
#pragma unroll
    for (int i = 0; i < 8; i++) {
        const int i2 = i >> 1;
        float4 o0, o1;
        if ((i & 1) == 0) {
            o0.x = lo32(accT[i2][0]) * s; o0.y = lo32(accT[i2][1]) * s;
            o0.z = lo32(accT[i2][2]) * s; o0.w = lo32(accT[i2][3]) * s;
            o1.x = lo32(accT[i2][4]) * s; o1.y = lo32(accT[i2][5]) * s;
            o1.z = lo32(accT[i2][6]) * s; o1.w = lo32(accT[i2][7]) * s;
        } else {
            o0.x = hi32(accT[i2][0]) * s; o0.y = hi32(accT[i2][1]) * s;
            o0.z = hi32(accT[i2][2]) * s; o0.w = hi32(accT[i2][3]) * s;
            o1.x = hi32(accT[i2][4]) * s; o1.y = hi32(accT[i2][5]) * s;
            o1.z = hi32(accT[i2][6]) * s; o1.w = hi32(accT[i2][7]) * s;
        }
        *(float4*)(Cp + (size_t)i * NC)     = o0;
        *(float4*)(Cp + (size_t)i * NC + 4) = o1;
    }
}

__global__ __launch_bounds__(256, 1) void k_gemm_fwd() {
    sgemm_body<Nv, Mv, false>(g_FR, g_Cm, g_CO);     // coeffs = frames @ Cm
}
__global__ __launch_bounds__(256, 1) void k_gemm_inv() {
    sgemm_body<Mv, Nv, true>(g_DQ, g_CmT, g_TD);     // td = (2/M) * dq @ Cm^T
}

// ---------------- per-(b,f) gain binary search (8 iters, integers) -------
__global__ void k_gain() {
    __shared__ float ax[2048];
    __shared__ float red[256];
    __shared__ float s_lo, s_hi;
    const int bf  = blockIdx.x;                 // rows (b,f,c): frame contiguous
    const int tid = threadIdx.x;
    const float* cf = g_CO + (size_t)bf * 2048;
    for (int i = tid; i < 2048; i += 256)
        ax[i] = powf(fabsf(cf[i]), 0.75f);
    if (tid == 0) { s_lo = 0.0f; s_hi = 120.0f; }
    __syncthreads();

    const float TARGET = (float)(128000.0 * 1024.0 / 48000.0); // 2730.666...
    for (int it = 0; it < 8; it++) {
        float mid = floorf((s_lo + s_hi) * 0.5f);
        float inv = exp2f((-0.75f * mid) / 4.0f);
        float bits = 0.0f;
        for (int i = tid; i < 2048; i += 256) {
            float qm = rintf(ax[i] * inv);
            bits += (qm > 0.0f) ? (floorf(log2f(fmaxf(qm, 1.0f))) + 2.0f) : 1.0f;
        }
        red[tid] = bits;
        __syncthreads();
        for (int s = 128; s > 0; s >>= 1) {
            if (tid < s) red[tid] += red[tid + s];
            __syncthreads();
        }
        if (tid == 0) {
            if (red[0] > TARGET) s_lo = mid + 1.0f;
            else                 s_hi = mid;
        }
        __syncthreads();
    }
    if (tid == 0) g_GA[bf] = s_hi;
}

// ---------------- quantize + dequantize (power-law) ---------------------
__global__ void k_quant() {
    int idx = blockIdx.x * blockDim.x + threadIdx.x;
    if (idx >= Rv * Mv) return;
    int bf = idx >> 11;                       // ((bf*2+c)*1024+m) >> 11 == bf
    float g     = g_GA[bf];
    float scale = exp2f(g / 4.0f);
    float cv    = g_CO[idx];
    float s1 = (cv > 0.0f) ? 1.0f : ((cv < 0.0f) ? -1.0f : 0.0f);
    float qs = s1 * powf(fabsf(cv) / scale + 1e-9f, 0.75f);
    float q  = rintf(qs);
    float s2 = (q > 0.0f) ? 1.0f : ((q < 0.0f) ? -1.0f : 0.0f);
    g_DQ[idx] = s2 * powf(fabsf(q), (float)(4.0 / 3.0)) * scale;
}

// ---------------- window + overlap-add + crop --------------------------
__global__ void k_ola(float* __restrict__ out) {
    int idx = blockIdx.x * blockDim.x + threadIdx.x;
    if (idx >= Bv * Cv * Tv) return;
    int t  = idx % Tv;
    int bc = idx / Tv;
    int b  = bc >> 1;
    int c  = bc & 1;
    int fb = t >> 10;           // second-half frame
    int na = t & 1023;
    int rowa = (b * Fv + fb + 1) * Cv + c;   // first-half frame (fb+1 <= 1407 < F)
    int rowb = (b * Fv + fb) * Cv + c;
    float r1 = g_TD[(size_t)rowa * Nv + na]      * g_W[na];
    float r2 = g_TD[(size_t)rowb * Nv + na + Mv] * g_W[na + Mv];
    out[idx] = r1 + r2;
}

// ---------------- launch ------------------------------------------------
extern "C" void kernel_launch(void* const* d_in, const int* in_sizes, int n_in,
                              void* d_out, int out_size) {
    const float* audio = (const float*)d_in[0];
    float* out = (float*)d_out;

    k_tables<<<(Nv * Mv + 255) / 256, 256>>>();
    {
        long long tot = (long long)Rv * Nv;
        k_frames<<<(unsigned)((tot + 255) / 256), 256>>>(audio);
    }
    k_gemm_fwd<<<dim3(Mv / 128, Rv / 128), 256>>>();
    k_gain<<<NFRAME, 256>>>();
    k_quant<<<(Rv * Mv + 255) / 256, 256>>>();
    k_gemm_inv<<<dim3(Nv / 128, Rv / 128), 256>>>();
    k_ola<<<(Bv * Cv * Tv + 255) / 256, 256>>>(out);
}

// round 9
// speedup vs baseline: 1.1703x; 1.1205x over previous
#include <cuda_runtime.h>
#include <math.h>
#include <stdint.h>

// ---------------- problem constants ----------------
#define Bv 8
#define Cv 2
#define Tv 1440000
#define Mv 1024
#define Nv 2048
#define Fv 1408
#define Rv (Bv*Fv*Cv)                // 22528 rows
#define NFRAME (Bv*Fv)               // 11264

// ---------------- static scratch ----------------
__device__ float g_W  [Nv];
__device__ float g_Cm [Nv*Mv];            // fwd B: [n 2048][m 1024] fp32
__device__ float g_Bih[Mv*Nv];            // inv B hi: [kdim=m 1024][col=n 2048]
__device__ float g_Bil[Mv*Nv];            // inv B lo
__device__ float g_FR [(size_t)Rv*Nv];    // fwd A fp32 (windowed frames)
__device__ float g_CO [(size_t)Rv*Mv];    // MDCT coeffs fp32
__device__ float g_GA [NFRAME];
__device__ float g_DQh[(size_t)Rv*Mv];    // inv A hi
__device__ float g_DQl[(size_t)Rv*Mv];    // inv A lo
__device__ float g_TD [(size_t)Rv*Nv];    // inverse transform fp32

// ---------------- helpers ----------------
__device__ __forceinline__ float tf32r(float x) {
    uint32_t u; asm("cvt.rna.tf32.f32 %0, %1;" : "=r"(u) : "f"(x));
    return __uint_as_float(u);
}
__device__ __forceinline__ uint64_t splat2(float x) {
    uint64_t r; uint32_t u = __float_as_uint(x);
    asm("mov.b64 %0, {%1, %1};" : "=l"(r) : "r"(u));
    return r;
}
__device__ __forceinline__ void ffma2(uint64_t& d, uint64_t a, uint64_t b) {
    asm("fma.rn.f32x2 %0, %1, %2, %0;" : "+l"(d) : "l"(a), "l"(b));
}
__device__ __forceinline__ void fadd2(uint64_t& d, uint64_t a) {
    asm("add.rn.f32x2 %0, %0, %1;" : "+l"(d) : "l"(a));
}
__device__ __forceinline__ float lo32(uint64_t v) {
    return __uint_as_float((uint32_t)(v & 0xffffffffu));
}
__device__ __forceinline__ float hi32(uint64_t v) {
    return __uint_as_float((uint32_t)(v >> 32));
}
__device__ __forceinline__ void mma8(float* d, const uint32_t* a, const uint32_t* b) {
    asm volatile(
        "mma.sync.aligned.m16n8k8.row.col.f32.tf32.tf32.f32 "
        "{%0,%1,%2,%3}, {%4,%5,%6,%7}, {%8,%9}, {%0,%1,%2,%3};"
        : "+f"(d[0]), "+f"(d[1]), "+f"(d[2]), "+f"(d[3])
        : "r"(a[0]), "r"(a[1]), "r"(a[2]), "r"(a[3]), "r"(b[0]), "r"(b[1]));
}
__device__ __forceinline__ void cpa16(uint32_t saddr, const void* g) {
    asm volatile("cp.async.cg.shared.global [%0], [%1], 16;"
                 :: "r"(saddr), "l"(g) : "memory");
}

// ---------------- tables: identical numerics to round 3 -----------------
__global__ void k_tables() {
    int idx = blockIdx.x * blockDim.x + threadIdx.x;
    if (idx >= Nv * Mv) return;
    int n = idx >> 10;
    int k = idx & 1023;
    const float c0 = (float)(3.14159265358979323846 / 1024.0);
    float a   = c0 * ((float)n + 512.5f);
    float arg = a * ((float)k + 0.5f);
    float v   = cosf(arg);
    g_Cm[n * Mv + k] = v;          // fwd B fp32
    float hi = tf32r(v);
    g_Bih[k * Nv + n] = hi;        // inv B split [m][n]
    g_Bil[k * Nv + n] = tf32r(v - hi);
    if (idx < Nv) {
        const float c1 = (float)(3.14159265358979323846 / 2048.0);
        g_W[idx] = sinf(c1 * ((float)idx + 0.5f));
    }
}

// ---------------- frame + window (fp32, as in round 3/4) -----------------
__global__ void k_frames(const float* __restrict__ audio) {
    long long idx = (long long)blockIdx.x * blockDim.x + threadIdx.x;
    if (idx >= (long long)Rv * Nv) return;
    int n   = (int)(idx & (Nv - 1));
    int row = (int)(idx >> 11);
    int c   = row & 1;
    int bf  = row >> 1;
    int f   = bf % Fv;
    int b   = bf / Fv;
    int src = f * Mv + n - Mv;
    float x = (src >= 0 && src < Tv)
                ? audio[(size_t)(b * Cv + c) * Tv + src] : 0.0f;
    g_FR[idx] = x * g_W[n];
}

// ---------------- fwd GEMM: R4's f32x2 FFMA kernel (bit-identical coeffs)
__device__ __forceinline__ void sgemm_fwd() {
    const float* __restrict__ A = g_FR;
    const float* __restrict__ B = g_Cm;
    float* __restrict__ Co = g_CO;
    constexpr int K = Nv, NC = Mv;
    __shared__ float As[2][8][128];
    __shared__ float Bs[2][8][128];
    const int tid  = threadIdx.x;
    const int bx   = blockIdx.x;
    const int by   = blockIdx.y;
    const int arow = tid >> 1;
    const int acol = (tid & 1) << 2;
    const int brow = tid >> 5;
    const int bcol = (tid & 31) << 2;
    const int tx   = tid & 15;
    const int ty   = tid >> 4;

    const float* Ap = A + (size_t)(by * 128 + arow) * K + acol;
    const float* Bp = B + (size_t)brow * NC + bx * 128 + bcol;

    uint64_t accT[4][8], accC[4][8];
#pragma unroll
    for (int i = 0; i < 4; i++)
#pragma unroll
        for (int j = 0; j < 8; j++) { accT[i][j] = 0ull; accC[i][j] = 0ull; }

    {
        float4 a4 = *(const float4*)Ap;
        float4 b4 = *(const float4*)Bp;
        As[0][acol + 0][arow] = a4.x;
        As[0][acol + 1][arow] = a4.y;
        As[0][acol + 2][arow] = a4.z;
        As[0][acol + 3][arow] = a4.w;
        *(float4*)&Bs[0][brow][bcol] = b4;
    }
    __syncthreads();

    const int NT = K / 8;
    int buf = 0;
#pragma unroll 1
    for (int t = 0; t < NT; ++t) {
        float4 na, nb4;
        const bool have_next = (t + 1 < NT);
        if (have_next) {
            na  = *(const float4*)(Ap + (size_t)(t + 1) * 8);
            nb4 = *(const float4*)(Bp + (size_t)(t + 1) * 8 * NC);
        }
#pragma unroll
        for (int k = 0; k < 8; k++) {
            uint64_t ap[4];
            {
                const ulonglong2* p2 = (const ulonglong2*)&As[buf][k][ty * 8];
                ulonglong2 v0 = p2[0], v1 = p2[1];
                ap[0] = v0.x; ap[1] = v0.y; ap[2] = v1.x; ap[3] = v1.y;
            }
            float rb[8];
            *(float4*)&rb[0] = *(const float4*)&Bs[buf][k][tx * 8];
            *(float4*)&rb[4] = *(const float4*)&Bs[buf][k][tx * 8 + 4];
            uint64_t bs[8];
#pragma unroll
            for (int j = 0; j < 8; j++) bs[j] = splat2(rb[j]);
#pragma unroll
            for (int i = 0; i < 4; i++)
#pragma unroll
                for (int j = 0; j < 8; j++)
                    ffma2(accC[i][j], ap[i], bs[j]);
        }
        if (((t + 1) & 31) == 0) {
#pragma unroll
            for (int i = 0; i < 4; i++)
#pragma unroll
                for (int j = 0; j < 8; j++) {
                    fadd2(accT[i][j], accC[i][j]);
                    accC[i][j] = 0ull;
                }
        }
        if (have_next) {
            int nbuf = buf ^ 1;
            As[nbuf][acol + 0][arow] = na.x;
            As[nbuf][acol + 1][arow] = na.y;
            As[nbuf][acol + 2][arow] = na.z;
            As[nbuf][acol + 3][arow] = na.w;
            *(float4*)&Bs[nbuf][brow][bcol] = nb4;
            __syncthreads();
            buf = nbuf;
        }
    }

    float* Cp = Co + (size_t)(by * 128 + ty * 8) * NC + bx * 128 + tx * 8;
#pragma unroll
    for (int i = 0; i < 8; i++) {
        const int i2 = i >> 1;
        float4 o0, o1;
        if ((i & 1) == 0) {
            o0.x = lo32(accT[i2][0]); o0.y = lo32(accT[i2][1]);
            o0.z = lo32(accT[i2][2]); o0.w = lo32(accT[i2][3]);
            o1.x = lo32(accT[i2][4]); o1.y = lo32(accT[i2][5]);
            o1.z = lo32(accT[i2][6]); o1.w = lo32(accT[i2][7]);
        } else {
            o0.x = hi32(accT[i2][0]); o0.y = hi32(accT[i2][1]);
            o0.z = hi32(accT[i2][2]); o0.w = hi32(accT[i2][3]);
            o1.x = hi32(accT[i2][4]); o1.y = hi32(accT[i2][5]);
            o1.z = hi32(accT[i2][6]); o1.w = hi32(accT[i2][7]);
        }
        *(float4*)(Cp + (size_t)i * NC)     = o0;
        *(float4*)(Cp + (size_t)i * NC + 4) = o1;
    }
}
__global__ __launch_bounds__(256, 1) void k_gemm_fwd() { sgemm_fwd(); }

// ---------------- inv GEMM: 3xTF32 mma.sync (error harmless here) --------
__device__ __forceinline__ void mma_inv() {
    const float* __restrict__ Agh = g_DQh;
    const float* __restrict__ Agl = g_DQl;
    const float* __restrict__ Bgh = g_Bih;
    const float* __restrict__ Bgl = g_Bil;
    float* __restrict__ Co = g_TD;
    constexpr int KTOT = Mv, NC = Nv;

    __shared__ float sAh[128 * 20];
    __shared__ float sAl[128 * 20];
    __shared__ float sBh[16 * 136];
    __shared__ float sBl[16 * 136];

    const int tid  = threadIdx.x;
    const int bx   = blockIdx.x, by = blockIdx.y;
    const int lane = tid & 31, wid = tid >> 5;
    const int wm   = (wid & 3) * 32;
    const int wn   = (wid >> 2) * 64;
    const int qr   = lane >> 2, qc = lane & 3;

    const uint32_t uAh = (uint32_t)__cvta_generic_to_shared(sAh);
    const uint32_t uAl = (uint32_t)__cvta_generic_to_shared(sAl);
    const uint32_t uBh = (uint32_t)__cvta_generic_to_shared(sBh);
    const uint32_t uBl = (uint32_t)__cvta_generic_to_shared(sBl);

    float acc[2][8][4];
#pragma unroll
    for (int i = 0; i < 2; i++)
#pragma unroll
        for (int j = 0; j < 8; j++)
#pragma unroll
            for (int c = 0; c < 4; c++) acc[i][j][c] = 0.0f;

    const int NST = KTOT / 16;
#pragma unroll 1
    for (int s = 0; s < NST; s++) {
        const int kt = s * 16;
        __syncthreads();
#pragma unroll
        for (int i = 0; i < 2; i++) {
            int idx = tid + i * 256;
            int r  = idx >> 2, k4 = idx & 3;
            size_t go = (size_t)(by * 128 + r) * KTOT + kt + k4 * 4;
            cpa16(uAh + (uint32_t)(r * 20 + k4 * 4) * 4, Agh + go);
            cpa16(uAl + (uint32_t)(r * 20 + k4 * 4) * 4, Agl + go);
            int kk = idx >> 5, n4 = idx & 31;
            size_t gb = (size_t)(kt + kk) * NC + bx * 128 + n4 * 4;
            cpa16(uBh + (uint32_t)(kk * 136 + n4 * 4) * 4, Bgh + gb);
            cpa16(uBl + (uint32_t)(kk * 136 + n4 * 4) * 4, Bgl + gb);
        }
        asm volatile("cp.async.commit_group;" ::: "memory");
        asm volatile("cp.async.wait_group 0;" ::: "memory");
        __syncthreads();

#pragma unroll
        for (int k8 = 0; k8 < 2; k8++) {
            uint32_t afh[2][4], afl[2][4];
#pragma unroll
            for (int mt = 0; mt < 2; mt++) {
                int r0 = wm + mt * 16 + qr;
                int c0 = k8 * 8 + qc;
                afh[mt][0] = __float_as_uint(sAh[(r0    ) * 20 + c0    ]);
                afh[mt][1] = __float_as_uint(sAh[(r0 + 8) * 20 + c0    ]);
                afh[mt][2] = __float_as_uint(sAh[(r0    ) * 20 + c0 + 4]);
                afh[mt][3] = __float_as_uint(sAh[(r0 + 8) * 20 + c0 + 4]);
                afl[mt][0] = __float_as_uint(sAl[(r0    ) * 20 + c0    ]);
                afl[mt][1] = __float_as_uint(sAl[(r0 + 8) * 20 + c0    ]);
                afl[mt][2] = __float_as_uint(sAl[(r0    ) * 20 + c0 + 4]);
                afl[mt][3] = __float_as_uint(sAl[(r0 + 8) * 20 + c0 + 4]);
            }
#pragma unroll
            for (int nt = 0; nt < 8; nt++) {
                int n0 = wn + nt * 8 + qr;
                int k0 = k8 * 8 + qc;
                uint32_t bfh[2], bfl[2];
                bfh[0] = __float_as_uint(sBh[(k0    ) * 136 + n0]);
                bfh[1] = __float_as_uint(sBh[(k0 + 4) * 136 + n0]);
                bfl[0] = __float_as_uint(sBl[(k0    ) * 136 + n0]);
                bfl[1] = __float_as_uint(sBl[(k0 + 4) * 136 + n0]);
#pragma unroll
                for (int mt = 0; mt < 2; mt++) {
                    mma8(acc[mt][nt], afh[mt], bfh);
                    mma8(acc[mt][nt], afh[mt], bfl);
                    mma8(acc[mt][nt], afl[mt], bfh);
                }
            }
        }
    }

    const float sc = 2.0f / 1024.0f;
#pragma unroll
    for (int mt = 0; mt < 2; mt++)
#pragma unroll
        for (int nt = 0; nt < 8; nt++) {
            int r  = by * 128 + wm + mt * 16 + qr;
            int cb = bx * 128 + wn + nt * 8 + qc * 2;
            float2 v0 = make_float2(acc[mt][nt][0] * sc, acc[mt][nt][1] * sc);
            float2 v1 = make_float2(acc[mt][nt][2] * sc, acc[mt][nt][3] * sc);
            *(float2*)(Co + (size_t)r * NC + cb)       = v0;
            *(float2*)(Co + (size_t)(r + 8) * NC + cb) = v1;
        }
}
__global__ __launch_bounds__(256, 2) void k_mma_inv() { mma_inv(); }

// ---------------- per-(b,f) gain binary search ---------------------------
__global__ void k_gain() {
    __shared__ float ax[2048];
    __shared__ float red[256];
    __shared__ float s_lo, s_hi;
    const int bf  = blockIdx.x;
    const int tid = threadIdx.x;
    const float* cf = g_CO + (size_t)bf * 2048;
    for (int i = tid; i < 2048; i += 256)
        ax[i] = powf(fabsf(cf[i]), 0.75f);
    if (tid == 0) { s_lo = 0.0f; s_hi = 120.0f; }
    __syncthreads();

    const float TARGET = (float)(128000.0 * 1024.0 / 48000.0);
    for (int it = 0; it < 8; it++) {
        float mid = floorf((s_lo + s_hi) * 0.5f);
        float inv = exp2f((-0.75f * mid) / 4.0f);
        float bits = 0.0f;
        for (int i = tid; i < 2048; i += 256) {
            float qm = rintf(ax[i] * inv);
            bits += (qm > 0.0f) ? (floorf(log2f(fmaxf(qm, 1.0f))) + 2.0f) : 1.0f;
        }
        red[tid] = bits;
        __syncthreads();
        for (int s = 128; s > 0; s >>= 1) {
            if (tid < s) red[tid] += red[tid + s];
            __syncthreads();
        }
        if (tid == 0) {
            if (red[0] > TARGET) s_lo = mid + 1.0f;
            else                 s_hi = mid;
        }
        __syncthreads();
    }
    if (tid == 0) g_GA[bf] = s_hi;
}

// ---------------- quantize + dequantize + tf32 split ---------------------
__global__ void k_quant() {
    int idx = blockIdx.x * blockDim.x + threadIdx.x;
    if (idx >= Rv * Mv) return;
    int bf = idx >> 11;
    float g     = g_GA[bf];
    float scale = exp2f(g / 4.0f);
    float cv    = g_CO[idx];
    float s1 = (cv > 0.0f) ? 1.0f : ((cv < 0.0f) ? -1.0f : 0.0f);
    float qs = s1 * powf(fabsf(cv) / scale + 1e-9f, 0.75f);
    float q  = rintf(qs);
    float s2 = (q > 0.0f) ? 1.0f : ((q < 0.0f) ? -1.0f : 0.0f);
    float v  = s2 * powf(fabsf(q), (float)(4.0 / 3.0)) * scale;
    float hi = tf32r(v);
    g_DQh[idx] = hi;
    g_DQl[idx] = tf32r(v - hi);
}

// ---------------- window + overlap-add + crop ----------------------------
__global__ void k_ola(float* __restrict__ out) {
    int idx = blockIdx.x * blockDim.x + threadIdx.x;
    if (idx >= Bv * Cv * Tv) return;
    int t  = idx % Tv;
    int bc = idx / Tv;
    int b  = bc >> 1;
    int c  = bc & 1;
    int fb = t >> 10;
    int na = t & 1023;
    int rowa = (b * Fv + fb + 1) * Cv + c;
    int rowb = (b * Fv + fb) * Cv + c;
    float r1 = g_TD[(size_t)rowa * Nv + na]      * g_W[na];
    float r2 = g_TD[(size_t)rowb * Nv + na + Mv] * g_W[na + Mv];
    out[idx] = r1 + r2;
}

// ---------------- launch --------------------------------------------------
extern "C" void kernel_launch(void* const* d_in, const int* in_sizes, int n_in,
                              void* d_out, int out_size) {
    const float* audio = (const float*)d_in[0];
    float* out = (float*)d_out;

    k_tables<<<(Nv * Mv + 255) / 256, 256>>>();
    {
        long long tot = (long long)Rv * Nv;
        k_frames<<<(unsigned)((tot + 255) / 256), 256>>>(audio);
    }
    k_gemm_fwd<<<dim3(Mv / 128, Rv / 128), 256>>>();
    k_gain<<<NFRAME, 256>>>();
    k_quant<<<(Rv * Mv + 255) / 256, 256>>>();
    k_mma_inv<<<dim3(Nv / 128, Rv / 128), 256>>>();
    k_ola<<<(Bv * Cv * Tv + 255) / 256, 256>>>(out);
}